// round 12
// baseline (speedup 1.0000x reference)
#include <cuda_runtime.h>
#include <cstdint>

#define N_ROWS   16384
#define D        1024
#define TEMPC    0.05f
#define EPSC     1e-8f

#define THREADS     256
#define ROWS_CTA    4
#define GRID        (N_ROWS / ROWS_CTA)          // 4096
#define STAGE_BYTES (ROWS_CTA * D * 4)           // 16 KB per input
#define F4_ROW      (D / 4)                      // 256 float4 per row

__device__ float g_partial[GRID];
__device__ unsigned int g_done = 0;

__device__ __forceinline__ uint32_t smem_u32(const void* p) {
    uint32_t a;
    asm("{ .reg .u64 t; cvta.to.shared.u64 t, %1; cvt.u32.u64 %0, t; }"
        : "=r"(a) : "l"(p));
    return a;
}

__global__ __launch_bounds__(THREADS) void byol_tma_kernel(
    const float* __restrict__ ga, const float* __restrict__ gb,
    float* __restrict__ out)
{
    __shared__ __align__(128) float sa[ROWS_CTA * D];
    __shared__ __align__(128) float sb[ROWS_CTA * D];
    __shared__ __align__(8)   unsigned long long mbar;

    const int t   = threadIdx.x;
    const int wid = t >> 5;
    const int lid = t & 31;

    const uint32_t mb = smem_u32(&mbar);

    if (t == 0) {
        asm volatile("mbarrier.init.shared.b64 [%0], %1;"
                     :: "r"(mb), "r"(1) : "memory");
    }
    __syncthreads();

    if (t == 0) {
        const long base = (long)blockIdx.x * (ROWS_CTA * D);
        asm volatile("mbarrier.arrive.expect_tx.shared.b64 _, [%0], %1;"
                     :: "r"(mb), "r"(2 * STAGE_BYTES) : "memory");
        asm volatile(
            "cp.async.bulk.shared::cta.global.mbarrier::complete_tx::bytes "
            "[%0], [%1], %2, [%3];"
            :: "r"(smem_u32(sa)), "l"(ga + base), "r"(STAGE_BYTES), "r"(mb)
            : "memory");
        asm volatile(
            "cp.async.bulk.shared::cta.global.mbarrier::complete_tx::bytes "
            "[%0], [%1], %2, [%3];"
            :: "r"(smem_u32(sb)), "l"(gb + base), "r"(STAGE_BYTES), "r"(mb)
            : "memory");
    }

    // Acquire-wait on TMA completion (parity 0; single-phase barrier)
    {
        uint32_t done;
        asm volatile(
            "{\n\t.reg .pred p;\n\t"
            "mbarrier.try_wait.parity.acquire.cta.shared::cta.b64 p, [%1], %2;\n\t"
            "selp.b32 %0, 1, 0, p;\n\t}"
            : "=r"(done) : "r"(mb), "r"(0) : "memory");
        if (!done) {
            asm volatile(
                "{\n\t.reg .pred P1;\n\t"
                "W_%=:\n\t"
                "mbarrier.try_wait.parity.acquire.cta.shared::cta.b64 P1, [%0], %1, 0x989680;\n\t"
                "@P1 bra.uni DONE_%=;\n\t"
                "bra.uni W_%=;\n\t"
                "DONE_%=:\n\t}"
                :: "r"(mb), "r"(0) : "memory");
        }
    }

    // Warp w: row = w/2, half = w%2 (512 floats = 128 float4; 4 per lane)
    const int row  = wid >> 1;
    const int half = wid & 1;
    const float4* sa4 = (const float4*)sa;
    const float4* sb4 = (const float4*)sb;
    const int base4 = row * F4_ROW + half * (F4_ROW / 2) + lid;

    float dot = 0.f, aa = 0.f, bb = 0.f;
    #pragma unroll
    for (int j = 0; j < 4; j++) {
        const float4 av = sa4[base4 + 32 * j];
        const float4 bv = sb4[base4 + 32 * j];
        dot += av.x * bv.x + av.y * bv.y + av.z * bv.z + av.w * bv.w;
        aa  += av.x * av.x + av.y * av.y + av.z * av.z + av.w * av.w;
        bb  += bv.x * bv.x + bv.y * bv.y + bv.z * bv.z + bv.w * bv.w;
    }

    #pragma unroll
    for (int off = 16; off > 0; off >>= 1) {
        dot += __shfl_xor_sync(0xffffffffu, dot, off);
        aa  += __shfl_xor_sync(0xffffffffu, aa,  off);
        bb  += __shfl_xor_sync(0xffffffffu, bb,  off);
    }

    __shared__ float s_dot[8], s_aa[8], s_bb[8], s_loss[ROWS_CTA];
    __shared__ bool  s_last;
    if (lid == 0) { s_dot[wid] = dot; s_aa[wid] = aa; s_bb[wid] = bb; }
    __syncthreads();

    if (t < ROWS_CTA) {                     // combine the two half-row warps
        const int w0 = 2 * t, w1 = 2 * t + 1;
        const float d  = s_dot[w0] + s_dot[w1];
        const float x  = s_aa[w0]  + s_aa[w1];
        const float y  = s_bb[w0]  + s_bb[w1];
        const float n1 = fmaxf(sqrtf(x), EPSC);
        const float n2 = fmaxf(sqrtf(y), EPSC);
        s_loss[t] = 2.0f - 2.0f * (d / (n1 * n2));
    }
    __syncthreads();

    if (t == 0) {
        float p = 0.f;
        #pragma unroll
        for (int r = 0; r < ROWS_CTA; r++) p += s_loss[r];   // fixed order
        g_partial[blockIdx.x] = p;
        __threadfence();
        const unsigned int prev = atomicAdd(&g_done, 1u);
        s_last = (prev == GRID - 1);
    }
    __syncthreads();

    // Last CTA: deterministic fixed-order reduce of 4096 partials
    if (s_last) {
        __shared__ float s[THREADS];
        float sum = 0.f;
        #pragma unroll
        for (int i = 0; i < GRID / THREADS; i++)             // 16 each
            sum += g_partial[t + i * THREADS];
        s[t] = sum;
        __syncthreads();
        #pragma unroll
        for (int off = THREADS / 2; off > 0; off >>= 1) {
            if (t < off) s[t] += s[t + off];
            __syncthreads();
        }
        if (t == 0) {
            out[0] = s[0] / ((float)N_ROWS * TEMPC);
            g_done = 0;   // reset for graph replay
        }
    }
}

extern "C" void kernel_launch(void* const* d_in, const int* in_sizes, int n_in,
                              void* d_out, int out_size)
{
    const float* ga = (const float*)d_in[0];  // online_output [16384,1024] f32
    const float* gb = (const float*)d_in[1];  // target_output [16384,1024] f32
    float* out = (float*)d_out;

    byol_tma_kernel<<<GRID, THREADS>>>(ga, gb, out);
}

// round 13
// speedup vs baseline: 1.0643x; 1.0643x over previous
#include <cuda_runtime.h>

#define N_ROWS   16384
#define D        1024
#define D4       (D / 4)          // 256 float4 per row
#define TEMPC    0.05f
#define EPSC     1e-8f

#define THREADS     512
#define WARPS_CTA   16
#define GRID        (N_ROWS / WARPS_CTA)   // 1024 CTAs, exactly 1 row per warp
#define F4_PER_LANE (D4 / 32)              // 8

__device__ float g_partial[GRID];
__device__ unsigned int g_done = 0;

__global__ __launch_bounds__(THREADS) void byol_v13_kernel(
    const float4* __restrict__ a4, const float4* __restrict__ b4,
    float* __restrict__ out)
{
    const int t   = threadIdx.x;
    const int wid = t >> 5;
    const int lid = t & 31;

    // Exactly one row per warp
    const int  row = blockIdx.x * WARPS_CTA + wid;
    const long idx = (long)row * D4 + lid;

    // Interleaved issue: both streams in flight immediately, 16 loads deep
    float4 av[F4_PER_LANE], bv[F4_PER_LANE];
    #pragma unroll
    for (int j = 0; j < F4_PER_LANE; j++) {
        av[j] = a4[idx + 32 * j];
        bv[j] = b4[idx + 32 * j];
    }

    float dot = 0.f, aa = 0.f, bb = 0.f;
    #pragma unroll
    for (int j = 0; j < F4_PER_LANE; j++) {
        dot += av[j].x * bv[j].x + av[j].y * bv[j].y
             + av[j].z * bv[j].z + av[j].w * bv[j].w;
        aa  += av[j].x * av[j].x + av[j].y * av[j].y
             + av[j].z * av[j].z + av[j].w * av[j].w;
        bb  += bv[j].x * bv[j].x + bv[j].y * bv[j].y
             + bv[j].z * bv[j].z + bv[j].w * bv[j].w;
    }

    #pragma unroll
    for (int off = 16; off > 0; off >>= 1) {
        dot += __shfl_xor_sync(0xffffffffu, dot, off);
        aa  += __shfl_xor_sync(0xffffffffu, aa,  off);
        bb  += __shfl_xor_sync(0xffffffffu, bb,  off);
    }

    // CTA combine (fixed warp order -> deterministic), one partial per CTA
    __shared__ float s_warp[WARPS_CTA];
    __shared__ bool  s_last;
    if (lid == 0) {
        const float n1 = fmaxf(sqrtf(aa), EPSC);
        const float n2 = fmaxf(sqrtf(bb), EPSC);
        s_warp[wid] = 2.0f - 2.0f * (dot / (n1 * n2));
    }
    __syncthreads();

    if (t == 0) {
        float p = 0.f;
        #pragma unroll
        for (int w = 0; w < WARPS_CTA; w++) p += s_warp[w];
        g_partial[blockIdx.x] = p;
        __threadfence();
        const unsigned int prev = atomicAdd(&g_done, 1u);
        s_last = (prev == GRID - 1);
    }
    __syncthreads();

    // Last CTA: deterministic fixed-order reduce of 1024 partials
    if (s_last) {
        __shared__ float s[THREADS];
        float sum = 0.f;
        #pragma unroll
        for (int i = 0; i < GRID / THREADS; i++)       // 2 each, fixed order
            sum += g_partial[t + i * THREADS];
        s[t] = sum;
        __syncthreads();
        #pragma unroll
        for (int off = THREADS / 2; off > 0; off >>= 1) {
            if (t < off) s[t] += s[t + off];
            __syncthreads();
        }
        if (t == 0) {
            out[0] = s[0] / ((float)N_ROWS * TEMPC);
            g_done = 0;   // reset for graph replay
        }
    }
}

extern "C" void kernel_launch(void* const* d_in, const int* in_sizes, int n_in,
                              void* d_out, int out_size)
{
    const float4* a4 = (const float4*)d_in[0];  // online_output [16384,1024] f32
    const float4* b4 = (const float4*)d_in[1];  // target_output [16384,1024] f32
    float* out = (float*)d_out;

    byol_v13_kernel<<<GRID, THREADS>>>(a4, b4, out);
}

// round 14
// speedup vs baseline: 1.1635x; 1.0932x over previous
#include <cuda_runtime.h>
#include <cstdint>

#define N_ROWS   16384
#define D        1024
#define D4       (D / 4)          // 256 float4 per row
#define TEMPC    0.05f
#define EPSC     1e-8f

#define THREADS     256
#define WARPS_CTA   8
#define GRID        (N_ROWS / WARPS_CTA)   // 2048 CTAs, exactly 1 row per warp
#define F4_PER_LANE (D4 / 32)              // 8

#define FP_SCALE    1073741824.0f          // 2^30 fixed-point
#define CNT_ONE     (1ULL << 52)           // completion count in high bits
#define SUM_MASK    (CNT_ONE - 1ULL)

// Single accumulator: low 52 bits fixed-point sum, bits >=52 CTA count.
// Integer adds are exact+commutative -> deterministic for any arrival order.
__device__ unsigned long long g_acc = 0ULL;

__global__ __launch_bounds__(THREADS) void byol_v14_kernel(
    const float4* __restrict__ a4, const float4* __restrict__ b4,
    float* __restrict__ out)
{
    const int t   = threadIdx.x;
    const int wid = t >> 5;
    const int lid = t & 31;

    const int  row = blockIdx.x * WARPS_CTA + wid;
    const long idx = (long)row * D4 + lid;

    // 16 front-batched interleaved LDG.128: both streams in flight at once
    float4 av[F4_PER_LANE], bv[F4_PER_LANE];
    #pragma unroll
    for (int j = 0; j < F4_PER_LANE; j++) {
        av[j] = a4[idx + 32 * j];
        bv[j] = b4[idx + 32 * j];
    }

    float dot = 0.f, aa = 0.f, bb = 0.f;
    #pragma unroll
    for (int j = 0; j < F4_PER_LANE; j++) {
        dot += av[j].x * bv[j].x + av[j].y * bv[j].y
             + av[j].z * bv[j].z + av[j].w * bv[j].w;
        aa  += av[j].x * av[j].x + av[j].y * av[j].y
             + av[j].z * av[j].z + av[j].w * av[j].w;
        bb  += bv[j].x * bv[j].x + bv[j].y * bv[j].y
             + bv[j].z * bv[j].z + bv[j].w * bv[j].w;
    }

    #pragma unroll
    for (int off = 16; off > 0; off >>= 1) {
        dot += __shfl_xor_sync(0xffffffffu, dot, off);
        aa  += __shfl_xor_sync(0xffffffffu, aa,  off);
        bb  += __shfl_xor_sync(0xffffffffu, bb,  off);
    }

    // CTA combine (fixed warp order -> deterministic contribution value)
    __shared__ float s_warp[WARPS_CTA];
    if (lid == 0) {
        const float n1 = fmaxf(sqrtf(aa), EPSC);
        const float n2 = fmaxf(sqrtf(bb), EPSC);
        s_warp[wid] = 2.0f - 2.0f * (dot / (n1 * n2));
    }
    __syncthreads();

    if (t == 0) {
        float p = 0.f;
        #pragma unroll
        for (int w = 0; w < WARPS_CTA; w++) p += s_warp[w];

        // Fixed-point contribution + completion count, one atomic total
        const unsigned long long contrib =
            (unsigned long long)llrintf(p * FP_SCALE) + CNT_ONE;
        const unsigned long long old = atomicAdd(&g_acc, contrib);

        if ((old >> 52) == (unsigned long long)(GRID - 1)) {
            // This CTA completes the sum: old + contrib is the grand total
            const unsigned long long total = (old + contrib) & SUM_MASK;
            out[0] = ((float)((double)total / (double)FP_SCALE))
                     / ((float)N_ROWS * TEMPC);
            g_acc = 0ULL;   // reset for graph replay (only reader/writer now)
        }
    }
}

extern "C" void kernel_launch(void* const* d_in, const int* in_sizes, int n_in,
                              void* d_out, int out_size)
{
    const float4* a4 = (const float4*)d_in[0];  // online_output [16384,1024] f32
    const float4* b4 = (const float4*)d_in[1];  // target_output [16384,1024] f32
    float* out = (float*)d_out;

    byol_v14_kernel<<<GRID, THREADS>>>(a4, b4, out);
}